// round 17
// baseline (speedup 1.0000x reference)
#include <cuda_runtime.h>
#include <cuda_bf16.h>
#include <cstdint>
#include <math.h>

// Problem constants
#define LL 128
#define BB 512
#define DD 512
#define SS 128
#define LB (LL * BB)   // 65536

// -------- device scratch --------
__device__ __align__(16) float          g_colbias[SS];
__device__ __align__(16) float          g_rvar[DD];
__device__ __align__(16) __nv_bfloat16  g_Mv[SS * DD];          // mu/var bf16, [s][d]
__device__ __align__(16) __nv_bfloat16  g_At[SS * SS];          // A^T bf16, [j][i]
// E bf16, layout [l][b>>3][j][b&7]  (16 MB)
__device__ __align__(16) __nv_bfloat16  g_E[(size_t)LL * 64 * 128 * 8];
__device__ __align__(16) float          g_dmaxT[BB * LL];       // dmax transposed: [b][l]
__device__ __align__(16) float          g_perb[BB];

#define LOG2PI 1.8378770664093453f
#define LOGPI_INIT (-4.852030263919617f)   // -log(128)

// ---- fast exp on the FMA pipe (x <= 0 expected; flushes below -80) ----
__device__ __forceinline__ float fexp(float x) {
    float t = fmaf(x, 1.4426950408889634f, 12582912.0f);
    int   ni = __float_as_int(t) - 0x4B400000;
    float n  = t - 12582912.0f;
    float f  = fmaf(x, 1.4426950408889634f, -n);
    float r  = 0.0013333558f;
    r = fmaf(r, f, 0.0096181291f);
    r = fmaf(r, f, 0.0555041087f);
    r = fmaf(r, f, 0.2402264689f);
    r = fmaf(r, f, 0.6931471806f);
    r = fmaf(r, f, 1.0f);
    float res = __int_as_float(__float_as_int(r) + (ni << 23));
    return (x > -80.0f) ? res : 0.0f;
}

__device__ __forceinline__ uint32_t pk(__nv_bfloat162 v) { return *reinterpret_cast<uint32_t*>(&v); }
__device__ __forceinline__ __nv_bfloat162 upk(uint32_t v) { return *reinterpret_cast<__nv_bfloat162*>(&v); }
__device__ __forceinline__ uint32_t smem_u32(const void* p) {
    return (uint32_t)__cvta_generic_to_shared(p);
}

__device__ __forceinline__ void mma_bf16(float& c0, float& c1, float& c2, float& c3,
                                         uint32_t a0, uint32_t a1, uint32_t a2, uint32_t a3,
                                         uint32_t b0, uint32_t b1) {
    asm volatile(
        "mma.sync.aligned.m16n8k16.row.col.f32.bf16.bf16.f32 "
        "{%0,%1,%2,%3}, {%4,%5,%6,%7}, {%8,%9}, {%0,%1,%2,%3};\n"
        : "+f"(c0), "+f"(c1), "+f"(c2), "+f"(c3)
        : "r"(a0), "r"(a1), "r"(a2), "r"(a3), "r"(b0), "r"(b1));
}

__device__ __forceinline__ void ldmx4(uint32_t& r0, uint32_t& r1, uint32_t& r2, uint32_t& r3,
                                      uint32_t addr) {
    asm volatile("ldmatrix.sync.aligned.m8n8.x4.shared.b16 {%0,%1,%2,%3}, [%4];"
                 : "=r"(r0), "=r"(r1), "=r"(r2), "=r"(r3) : "r"(addr));
}

// =====================================================================
// Kernel 1: preprocessing (1 block, 512 threads)
// =====================================================================
__global__ void prep_kernel(const float* __restrict__ tparams,
                            const float* __restrict__ means,
                            const float* __restrict__ var) {
    __shared__ float sred[512];
    int t = threadIdx.x;

    float v = var[t];
    g_rvar[t] = 1.0f / v;
    sred[t] = logf(v);
    __syncthreads();
    for (int off = 256; off > 0; off >>= 1) {
        if (t < off) sred[t] += sred[t + off];
        __syncthreads();
    }
    float slv = sred[0];
    float c = -256.0f * LOG2PI - 0.5f * slv;

    int q   = t & 3;      // 0..3
    int grp = t >> 2;     // 0..127  (row i)

    // col bias
    {
        float mq = 0.f;
        for (int d = q; d < DD; d += 4) {
            float m = means[grp * DD + d];
            mq += m * m * g_rvar[d];
        }
        mq += __shfl_xor_sync(0xffffffffu, mq, 1);
        mq += __shfl_xor_sync(0xffffffffu, mq, 2);
        if (q == 0) g_colbias[grp] = c - 0.5f * mq;
    }

    // At[j][i] = exp(tparams[i][j] - lse_j'(tparams[i][:]))
    {
        float mx = -1e30f;
        for (int jj = q; jj < SS; jj += 4) mx = fmaxf(mx, tparams[grp * SS + jj]);
        mx = fmaxf(mx, __shfl_xor_sync(0xffffffffu, mx, 1));
        mx = fmaxf(mx, __shfl_xor_sync(0xffffffffu, mx, 2));
        float se = 0.f;
        for (int jj = q; jj < SS; jj += 4) se += __expf(tparams[grp * SS + jj] - mx);
        se += __shfl_xor_sync(0xffffffffu, se, 1);
        se += __shfl_xor_sync(0xffffffffu, se, 2);
        float lse = mx + __logf(se);
        for (int jj = q; jj < SS; jj += 4)
            g_At[jj * SS + grp] = __float2bfloat16(__expf(tparams[grp * SS + jj] - lse));
    }

    // Mv = mu / var in bf16
    for (int idx = t; idx < SS * DD; idx += 512) {
        int d = idx & (DD - 1);
        g_Mv[idx] = __float2bfloat16(means[idx] * g_rvar[d]);
    }
}

// =====================================================================
// Kernel 2: FUSED density — reads fp32 sents directly, converts to bf16
// during staging, accumulates x^2/var in registers (one reduce at end).
// 2D warp tiling (4m x 2n), full ldmatrix mainloop.
// E staged in retired sA smem, then block-copied (32KB contig).
// =====================================================================
#define SMSTRIDE 72

__global__ __launch_bounds__(256) void density_kernel(const float* __restrict__ sents) {
    __shared__ __align__(16) __nv_bfloat16 sA[128 * SMSTRIDE];
    __shared__ __align__(16) __nv_bfloat16 sB[128 * SMSTRIDE];
    __shared__ __align__(16) float srv[DD];
    __shared__ float scb[128];
    __shared__ float sMX[2][128];
    __shared__ float sXQ[128];

    int tid  = threadIdx.x;
    int warp = tid >> 5, lane = tid & 31;
    int g = lane >> 2, tg = lane & 3;
    int warp_m = warp >> 1, warp_n = warp & 1;
    int mbase = blockIdx.x * 128;

    if (tid < 128) scb[tid] = g_colbias[tid];
    for (int i = tid; i < DD; i += 256) srv[i] = g_rvar[i];

    int arow = (lane & 7) + ((lane & 8) ? 8 : 0);
    int akof = (lane & 16) ? 8 : 0;
    int q = lane >> 3, r = lane & 7;
    int rowb = ((q & 2) ? 8 : 0) + r;
    int kofs = (q & 1) ? 8 : 0;

    uint32_t sa_base = smem_u32(sA);
    uint32_t sb_base = smem_u32(sB);

    float acc[2][8][4];
#pragma unroll
    for (int mt = 0; mt < 2; ++mt)
#pragma unroll
        for (int n = 0; n < 8; ++n)
#pragma unroll
            for (int k = 0; k < 4; ++k) acc[mt][n][k] = 0.f;

    // per-thread xq partials; slot k always maps to row (tid + k*256)>>3
    float xqp[4];
    xqp[0] = xqp[1] = xqp[2] = xqp[3] = 0.f;

    __syncthreads();

    for (int ko = 0; ko < 8; ++ko) {
        // ---- stage A from fp32 sents: convert + accumulate x^2/var ----
#pragma unroll
        for (int k = 0; k < 4; ++k) {
            int idx = tid + k * 256;
            int rr = idx >> 3, c8 = idx & 7;
            const float* srcp = &sents[(size_t)(mbase + rr) * DD + ko * 64 + c8 * 8];
            float4 x0 = *reinterpret_cast<const float4*>(srcp);
            float4 x1 = *reinterpret_cast<const float4*>(srcp + 4);
            const float* rvp = &srv[ko * 64 + c8 * 8];
            float4 r0 = *reinterpret_cast<const float4*>(rvp);
            float4 r1 = *reinterpret_cast<const float4*>(rvp + 4);
            xqp[k] += x0.x * x0.x * r0.x + x0.y * x0.y * r0.y
                    + x0.z * x0.z * r0.z + x0.w * x0.w * r0.w
                    + x1.x * x1.x * r1.x + x1.y * x1.y * r1.y
                    + x1.z * x1.z * r1.z + x1.w * x1.w * r1.w;
            uint4 pkd;
            pkd.x = pk(__float22bfloat162_rn(make_float2(x0.x, x0.y)));
            pkd.y = pk(__float22bfloat162_rn(make_float2(x0.z, x0.w)));
            pkd.z = pk(__float22bfloat162_rn(make_float2(x1.x, x1.y)));
            pkd.w = pk(__float22bfloat162_rn(make_float2(x1.z, x1.w)));
            *reinterpret_cast<uint4*>(&sA[rr * SMSTRIDE + c8 * 8]) = pkd;
        }
        // ---- stage B (bf16 copies of Mv) ----
#pragma unroll
        for (int k = 0; k < 4; ++k) {
            int idx = tid + k * 256;
            int rr = idx >> 3, c8 = idx & 7;
            uint4 vb = *reinterpret_cast<const uint4*>(&g_Mv[(size_t)rr * DD + ko * 64 + c8 * 8]);
            *reinterpret_cast<uint4*>(&sB[rr * SMSTRIDE + c8 * 8]) = vb;
        }
        __syncthreads();

#pragma unroll
        for (int ks = 0; ks < 4; ++ks) {
            int kb = ks * 16;
            uint32_t afr[2][4];
#pragma unroll
            for (int mt = 0; mt < 2; ++mt)
                ldmx4(afr[mt][0], afr[mt][1], afr[mt][2], afr[mt][3],
                      sa_base + ((warp_m * 32 + mt * 16 + arow) * SMSTRIDE + kb + akof) * 2);
#pragma unroll
            for (int npair = 0; npair < 4; ++npair) {
                uint32_t t0, t1, t2, t3;
                ldmx4(t0, t1, t2, t3,
                      sb_base + ((warp_n * 64 + npair * 16 + rowb) * SMSTRIDE + kb + kofs) * 2);
#pragma unroll
                for (int mt = 0; mt < 2; ++mt) {
                    mma_bf16(acc[mt][2 * npair][0], acc[mt][2 * npair][1],
                             acc[mt][2 * npair][2], acc[mt][2 * npair][3],
                             afr[mt][0], afr[mt][1], afr[mt][2], afr[mt][3], t0, t1);
                    mma_bf16(acc[mt][2 * npair + 1][0], acc[mt][2 * npair + 1][1],
                             acc[mt][2 * npair + 1][2], acc[mt][2 * npair + 1][3],
                             afr[mt][0], afr[mt][1], afr[mt][2], afr[mt][3], t2, t3);
                }
            }
        }
        __syncthreads();
    }

    // ---- xq reduce: 8 consecutive threads share each row (one-time) ----
#pragma unroll
    for (int k = 0; k < 4; ++k) {
        float s = xqp[k];
        s += __shfl_xor_sync(0xffffffffu, s, 1);
        s += __shfl_xor_sync(0xffffffffu, s, 2);
        s += __shfl_xor_sync(0xffffffffu, s, 4);
        if ((lane & 7) == 0) sXQ[(tid + k * 256) >> 3] = -0.5f * s;
    }

    // colbias + row maxes
    float mx[2][2];
    mx[0][0] = mx[0][1] = mx[1][0] = mx[1][1] = -1e30f;
#pragma unroll
    for (int mt = 0; mt < 2; ++mt)
#pragma unroll
        for (int n = 0; n < 8; ++n) {
            int cglob = (warp_n * 8 + n) * 8 + tg * 2;
            float cb0 = scb[cglob], cb1 = scb[cglob + 1];
            acc[mt][n][0] += cb0; acc[mt][n][1] += cb1;
            acc[mt][n][2] += cb0; acc[mt][n][3] += cb1;
            mx[mt][0] = fmaxf(mx[mt][0], fmaxf(acc[mt][n][0], acc[mt][n][1]));
            mx[mt][1] = fmaxf(mx[mt][1], fmaxf(acc[mt][n][2], acc[mt][n][3]));
        }
#pragma unroll
    for (int mt = 0; mt < 2; ++mt)
#pragma unroll
        for (int h = 0; h < 2; ++h) {
            mx[mt][h] = fmaxf(mx[mt][h], __shfl_xor_sync(0xffffffffu, mx[mt][h], 1));
            mx[mt][h] = fmaxf(mx[mt][h], __shfl_xor_sync(0xffffffffu, mx[mt][h], 2));
        }
    if (tg == 0) {
#pragma unroll
        for (int mt = 0; mt < 2; ++mt) {
            int rbase = warp_m * 32 + mt * 16;
            sMX[warp_n][rbase + g]     = mx[mt][0];
            sMX[warp_n][rbase + g + 8] = mx[mt][1];
        }
    }
    __syncthreads();

    int l = mbase >> 9;
    int bl0 = mbase & (BB - 1);    // first batch of this tile

    // write E into staging (reuse sA): stage[(b_local>>3)*1024 + j*8 + (b_local&7)]
    __nv_bfloat16* stage = sA;
#pragma unroll
    for (int mt = 0; mt < 2; ++mt) {
        int rbase = warp_m * 32 + mt * 16;
        float fmx0 = fmaxf(sMX[0][rbase + g], sMX[1][rbase + g]);
        float fmx1 = fmaxf(sMX[0][rbase + g + 8], sMX[1][rbase + g + 8]);
        int base0 = ((rbase >> 3)) * 1024 + g;        // b_local = rbase+g
        int base1 = ((rbase >> 3) + 1) * 1024 + g;    // b_local = rbase+g+8
#pragma unroll
        for (int n = 0; n < 8; ++n) {
            int j0 = (warp_n * 8 + n) * 8 + 2 * tg;
            stage[base0 + j0 * 8]       = __float2bfloat16(fexp(acc[mt][n][0] - fmx0));
            stage[base0 + (j0 + 1) * 8] = __float2bfloat16(fexp(acc[mt][n][1] - fmx0));
            stage[base1 + j0 * 8]       = __float2bfloat16(fexp(acc[mt][n][2] - fmx1));
            stage[base1 + (j0 + 1) * 8] = __float2bfloat16(fexp(acc[mt][n][3] - fmx1));
        }
        if (warp_n == 0 && tg == 0) {
            int rl = rbase + g;
            int b = (mbase + rl) & (BB - 1);
            g_dmaxT[(size_t)b * LL + l]       = fmx0 + sXQ[rl];
            g_dmaxT[(size_t)(b + 8) * LL + l] = fmx1 + sXQ[rl + 8];
        }
    }
    __syncthreads();

    // contiguous 32 KB copy out
    uint4* dst = reinterpret_cast<uint4*>(g_E + ((size_t)l * 64 + (bl0 >> 3)) * 1024);
    const uint4* srcp = reinterpret_cast<const uint4*>(stage);
    for (int i = tid; i < 2048; i += 256) dst[i] = srcp[i];
}

// =====================================================================
// Kernel 3: forward recurrence — TRANSPOSED: out(j,b) = At(j,i) @ pT(i,b).
// 64 CTAs x 256 threads, 8 batches/CTA. Warp w owns j in [16w,16w+16).
// Split accumulator: two independent 4-deep HMMA chains (kt 0-3 / 4-7).
// =====================================================================
#define ATSTRIDE 136
#define PSTRIDE  136

__global__ __launch_bounds__(256) void recur_kernel(const float* __restrict__ masks) {
    __shared__ __align__(16) __nv_bfloat16 sAt[128 * ATSTRIDE];  // 34816 B
    __shared__ __align__(16) __nv_bfloat16 sP[2][8 * PSTRIDE];   // 2 x 2176 B
    __shared__ float sdmax[LL * 8];                              // 4096 B
    __shared__ unsigned char smk[LL * 8];                        // 1024 B
    __shared__ float srn[8][8];
    __shared__ float ssum[8][8];
    __shared__ float sM[8];

    int tid   = threadIdx.x;
    int lane  = tid & 31, w = tid >> 5;     // w in [0,8) = m-tile (j group)
    int b8    = blockIdx.x;                  // 0..63
    int b0    = b8 * 8;
    int g = lane >> 2, tg = lane & 3;

    {
        const uint4* src = reinterpret_cast<const uint4*>(g_At);
        for (int idx = tid; idx < 2048; idx += 256) {
            int j = idx >> 4, c = idx & 15;
            *reinterpret_cast<uint4*>(&sAt[j * ATSTRIDE + c * 8]) = src[idx];
        }
    }
    for (int idx = tid; idx < 1024; idx += 256) {
        int bi = idx >> 7, l = idx & 127;
        sdmax[l * 8 + bi] = g_dmaxT[(size_t)(b0 + bi) * LL + l];
        smk[l * 8 + bi]   = (masks[l * BB + b0 + bi] >= 0.5f) ? 1 : 0;
    }
    __syncthreads();

    // hoist At fragments for own m-tile (j in [16w,16w+16))
    int arow = (lane & 7) + ((lane & 8) ? 8 : 0);
    int akof = (lane & 16) ? 8 : 0;
    uint32_t af[32];
#pragma unroll
    for (int kt = 0; kt < 8; ++kt)
        ldmx4(af[kt * 4 + 0], af[kt * 4 + 1], af[kt * 4 + 2], af[kt * 4 + 3],
              smem_u32(&sAt[(16 * w + arow) * ATSTRIDE + kt * 16 + akof]));

    int j0 = 16 * w + g;
    int j1 = j0 + 8;

    // init: p = E[0]
    uint32_t pv01, pv23;   // {b=2tg, b=2tg+1} for rows j0 / j1
    {
        const __nv_bfloat16* E0 = g_E + (size_t)b8 * 1024;
        pv01 = *reinterpret_cast<const uint32_t*>(&E0[j0 * 8 + 2 * tg]);
        pv23 = *reinterpret_cast<const uint32_t*>(&E0[j1 * 8 + 2 * tg]);
        __nv_bfloat162 v01 = upk(pv01), v23 = upk(pv23);
        sP[0][(2 * tg) * PSTRIDE + j0]     = __low2bfloat16(v01);
        sP[0][(2 * tg + 1) * PSTRIDE + j0] = __high2bfloat16(v01);
        sP[0][(2 * tg) * PSTRIDE + j1]     = __low2bfloat16(v23);
        sP[0][(2 * tg + 1) * PSTRIDE + j1] = __high2bfloat16(v23);
    }
    float Mb0 = LOGPI_INIT + sdmax[2 * tg];
    float Mb1 = LOGPI_INIT + sdmax[2 * tg + 1];
    __syncthreads();

    // B-frag ldmatrix lane addresses over sP: [b rows][i cols]
    int br = lane & 7, bq = lane >> 3;
    uint32_t pb[2];
    pb[0] = smem_u32(&sP[0][br * PSTRIDE + 8 * bq]);
    pb[1] = smem_u32(&sP[1][br * PSTRIDE + 8 * bq]);

    int buf = 0;
    for (int l = 1; l < LL; ++l) {
        // B fragments: 4 x ldmx4 covering kt pairs
        uint32_t bfr[16];
#pragma unroll
        for (int ks = 0; ks < 4; ++ks)
            ldmx4(bfr[ks * 4 + 0], bfr[ks * 4 + 1], bfr[ks * 4 + 2], bfr[ks * 4 + 3],
                  pb[buf] + ks * 64);      // 32 halfs = 64 B per ks

        const __nv_bfloat16* El = g_E + ((size_t)l * 64 + b8) * 1024;
        uint32_t e01 = *reinterpret_cast<const uint32_t*>(&El[j0 * 8 + 2 * tg]);
        uint32_t e23 = *reinterpret_cast<const uint32_t*>(&El[j1 * 8 + 2 * tg]);

        float dm0 = sdmax[l * 8 + 2 * tg];
        float dm1 = sdmax[l * 8 + 2 * tg + 1];
        int mk0 = smk[l * 8 + 2 * tg];
        int mk1 = smk[l * 8 + 2 * tg + 1];

        // two independent 4-deep chains
        float a0c = 0.f, a1c = 0.f, a2c = 0.f, a3c = 0.f;
        float b0c = 0.f, b1c = 0.f, b2c = 0.f, b3c = 0.f;
#pragma unroll
        for (int kt = 0; kt < 4; ++kt)
            mma_bf16(a0c, a1c, a2c, a3c,
                     af[kt * 4 + 0], af[kt * 4 + 1], af[kt * 4 + 2], af[kt * 4 + 3],
                     bfr[kt * 2 + 0], bfr[kt * 2 + 1]);
#pragma unroll
        for (int kt = 4; kt < 8; ++kt)
            mma_bf16(b0c, b1c, b2c, b3c,
                     af[kt * 4 + 0], af[kt * 4 + 1], af[kt * 4 + 2], af[kt * 4 + 3],
                     bfr[kt * 2 + 0], bfr[kt * 2 + 1]);
        float c0 = a0c + b0c, c1 = a1c + b1c, c2 = a2c + b2c, c3 = a3c + b3c;

        // epilogue: * E, per-batch-column mask blend
        float2 eg = __bfloat1622float2(upk(e01));
        float2 eh = __bfloat1622float2(upk(e23));
        float n0 = c0 * eg.x, n1 = c1 * eg.y;
        float n2 = c2 * eh.x, n3 = c3 * eh.y;
        float2 p01 = __bfloat1622float2(upk(pv01));
        float2 p23 = __bfloat1622float2(upk(pv23));
        if (!mk0) { n0 = p01.x; n2 = p23.x; }
        if (!mk1) { n1 = p01.y; n3 = p23.y; }
        if (mk0) Mb0 += dm0;
        if (mk1) Mb1 += dm1;

        // periodic renorm: per-batch max over all j
        if ((l & 7) == 0) {
            float m0 = fmaxf(1e-30f, fmaxf(n0, n2));
            float m1 = fmaxf(1e-30f, fmaxf(n1, n3));
#pragma unroll
            for (int off = 4; off <= 16; off <<= 1) {
                m0 = fmaxf(m0, __shfl_xor_sync(0xffffffffu, m0, off));
                m1 = fmaxf(m1, __shfl_xor_sync(0xffffffffu, m1, off));
            }
            if (lane < 4) { srn[w][2 * tg] = m0; srn[w][2 * tg + 1] = m1; }
            __syncthreads();
#pragma unroll
            for (int ww = 0; ww < 8; ++ww) {
                m0 = fmaxf(m0, srn[ww][2 * tg]);
                m1 = fmaxf(m1, srn[ww][2 * tg + 1]);
            }
            float r0i = 1.f / m0, r1i = 1.f / m1;
            n0 *= r0i; n2 *= r0i;
            n1 *= r1i; n3 *= r1i;
            Mb0 += __logf(m0);
            Mb1 += __logf(m1);
        }

        pv01 = pk(__floats2bfloat162_rn(n0, n1));
        pv23 = pk(__floats2bfloat162_rn(n2, n3));

        int nbuf = buf ^ 1;
        {
            __nv_bfloat16* base = sP[nbuf];
            base[(2 * tg) * PSTRIDE + j0]     = __float2bfloat16(n0);
            base[(2 * tg + 1) * PSTRIDE + j0] = __float2bfloat16(n1);
            base[(2 * tg) * PSTRIDE + j1]     = __float2bfloat16(n2);
            base[(2 * tg + 1) * PSTRIDE + j1] = __float2bfloat16(n3);
        }
        __syncthreads();
        buf = nbuf;
    }

    // objective per batch: M + log(sum_j p_j)
    float2 p01 = __bfloat1622float2(upk(pv01));
    float2 p23 = __bfloat1622float2(upk(pv23));
    float S0 = p01.x + p23.x;
    float S1 = p01.y + p23.y;
#pragma unroll
    for (int off = 4; off <= 16; off <<= 1) {
        S0 += __shfl_xor_sync(0xffffffffu, S0, off);
        S1 += __shfl_xor_sync(0xffffffffu, S1, off);
    }
    if (lane < 4) {
        ssum[w][2 * tg] = S0;
        ssum[w][2 * tg + 1] = S1;
        if (w == 0) { sM[2 * tg] = Mb0; sM[2 * tg + 1] = Mb1; }
    }
    __syncthreads();
    if (tid < 8) {
        float S = 0.f;
#pragma unroll
        for (int ww = 0; ww < 8; ++ww) S += ssum[ww][tid];
        S = fmaxf(S, 1e-37f);
        g_perb[b0 + tid] = sM[tid] + __logf(S);
    }
}

// =====================================================================
// Kernel 4: deterministic final reduction over 512 batch rows
// =====================================================================
__global__ void finalize_kernel(float* __restrict__ out, int out_size) {
    __shared__ float s[256];
    int t = threadIdx.x;
    s[t] = g_perb[t] + g_perb[t + 256];
    __syncthreads();
    for (int off = 128; off > 0; off >>= 1) {
        if (t < off) s[t] += s[t + off];
        __syncthreads();
    }
    for (int i = t; i < out_size; i += 256)
        if (i != 0) out[i] = 0.f;   // jacobian_loss = 0
    if (t == 0) out[0] = s[0];
}

// =====================================================================
extern "C" void kernel_launch(void* const* d_in, const int* in_sizes, int n_in,
                              void* d_out, int out_size) {
    const float* sents   = (const float*)d_in[0];
    const float* masks   = (const float*)d_in[1];
    const float* tparams = (const float*)d_in[2];
    const float* means   = (const float*)d_in[3];
    const float* var     = (const float*)d_in[4];
    float* out = (float*)d_out;

    prep_kernel<<<1, 512>>>(tparams, means, var);
    density_kernel<<<LB / 128, 256>>>(sents);
    recur_kernel<<<64, 256>>>(masks);
    finalize_kernel<<<1, 256>>>(out, out_size);
}